// round 15
// baseline (speedup 1.0000x reference)
#include <cuda_runtime.h>

#define BATCH 32
#define IMH 1024
#define IMW 1024
#define NBOX 96
#define WARPS 8
#define NTHREADS 256
#define ROWS_PER_WARP 4
#define ROWS_PER_BLOCK (WARPS * ROWS_PER_WARP)   // 32
#define GRID (BATCH * IMH / ROWS_PER_BLOCK)      // 1024
#define EP_STRIDE 1032                           // >=1024, float4-aligned

// Per-(batch,box) rectangle sums. Zero-initialized at module load; the last
// block resets it after reading so every graph replay starts clean.
__device__ float    g_boxsum[BATCH * NBOX];
__device__ unsigned g_done;

__global__ __launch_bounds__(NTHREADS)
void fused_kernel(const float* __restrict__ img, const int* __restrict__ bb,
                  float* __restrict__ out) {
    // Double-buffered per-warp prefix rows: removes the trailing WAR-guard
    // __syncwarp each row, letting box sampling overlap the next row's
    // prefetch/scan/STS.
    __shared__ __align__(16) float ep_s[2 * WARPS * EP_STRIDE];
    __shared__ int4 sbox[NBOX];

    const int t    = threadIdx.x;
    const int lane = t & 31;
    const int w    = t >> 5;
    const int blocksPerBatch = IMH / ROWS_PER_BLOCK;   // 32
    const int b       = blockIdx.x / blocksPerBatch;
    const int rowBase = (blockIdx.x % blocksPerBatch) * ROWS_PER_BLOCK + w * ROWS_PER_WARP;

    float* ep0 = ep_s + (2 * w + 0) * EP_STRIDE;
    float* ep1 = ep_s + (2 * w + 1) * EP_STRIDE;

    const float4* imgrow = (const float4*)(img + (size_t)b * IMH * IMW);

    // First-row loads issued before the bbox sync (prologue overlap).
    float4 va[8];
#pragma unroll
    for (int j = 0; j < 8; j++)
        va[j] = imgrow[(size_t)rowBase * (IMW / 4) + lane + 32 * j];

    if (t < NBOX) sbox[t] = ((const int4*)bb)[b * NBOX + t];
    __syncthreads();

    // Each lane serves boxes lane, lane+32, lane+64. Packed state (3 regs/box):
    // px = x1 | x2<<16, py = y1 | y2<<16, bacc. Invalid boxes get y1=y2=0 ->
    // never served -> accumulate exactly 0, matching the reference mask.
    int   px[3], py[3];
    float bacc[3];
#pragma unroll
    for (int k = 0; k < 3; k++) {
        int4 box = sbox[lane + 32 * k];
        int x1 = min(max(box.x, 0), IMW);
        int y1 = min(max(box.y, 0), IMW);
        int x2 = min(max(box.z, 0), IMW);
        int y2 = min(max(box.w, 0), IMW);
        if (!((x2 > x1) && (y2 > y1))) { y1 = 0; y2 = 0; }
        px[k] = x1 | (x2 << 16);
        py[k] = y1 | (y2 << 16);
        bacc[k] = 0.0f;
    }

#pragma unroll
    for (int r = 0; r < ROWS_PER_WARP; ++r) {
        const int row = rowBase + r;
        float* ep = (r & 1) ? ep1 : ep0;

        // Register prefetch of next row (overlaps this row's scan).
        float4 vb[8];
        if (r + 1 < ROWS_PER_WARP) {
#pragma unroll
            for (int j = 0; j < 8; j++)
                vb[j] = imgrow[(size_t)(row + 1) * (IMW / 4) + lane + 32 * j];
        }

        // Per-(lane, segment) 4-element sums.
        float s[8], sc[8];
#pragma unroll
        for (int j = 0; j < 8; j++) {
            s[j]  = (va[j].x + va[j].y) + (va[j].z + va[j].w);
            sc[j] = s[j];
        }

        // Eight CONCURRENT Kogge-Stone scans (o-outer, j-inner: the 8
        // independent shfl chains pipeline in the SMSP).
#pragma unroll
        for (int o = 1; o < 32; o <<= 1) {
#pragma unroll
            for (int j = 0; j < 8; j++) {
                float u = __shfl_up_sync(0xffffffffu, sc[j], o);
                if (lane >= o) sc[j] += u;
            }
        }

        // Segment totals via 8 parallel broadcasts + short scalar prefix.
        float T[8];
#pragma unroll
        for (int j = 0; j < 8; j++)
            T[j] = __shfl_sync(0xffffffffu, sc[j], 31);
        float basej[8];
        basej[0] = 0.0f;
#pragma unroll
        for (int j = 1; j < 8; j++)
            basej[j] = basej[j - 1] + T[j - 1];
        const float rowtot = basej[7] + T[7];   // warp-uniform: prefix(1024)

        // Write exclusive prefixes: 8 conflict-free STS.128 per row.
#pragma unroll
        for (int j = 0; j < 8; j++) {
            float excl = (sc[j] - s[j]) + basej[j];
            float4 p;
            p.x = excl;
            p.y = p.x + va[j].x;
            p.z = p.y + va[j].y;
            p.w = p.z + va[j].z;
            *(float4*)(ep + 128 * j + 4 * lane) = p;
        }
        __syncwarp();   // cross-lane visibility of this row's prefixes

        // Serve this row for all 96 boxes (3 per lane). Single unsigned
        // compare for the y-range; x2==1024 uses the register row total.
        // No trailing sync: next row writes the OTHER buffer.
#pragma unroll
        for (int k = 0; k < 3; k++) {
            const int y1 = py[k] & 0xffff;
            if ((unsigned)(row - y1) < (unsigned)((py[k] >> 16) - y1)) {
                const int x1 = px[k] & 0xffff, x2 = px[k] >> 16;
                float right = (x2 == IMW) ? rowtot : ep[x2];
                bacc[k] += right - ep[x1];
            }
        }

        if (r + 1 < ROWS_PER_WARP) {
#pragma unroll
            for (int j = 0; j < 8; j++)
                va[j] = vb[j];
        }
    }

#pragma unroll
    for (int k = 0; k < 3; k++)
        if (bacc[k] != 0.0f)
            atomicAdd(&g_boxsum[b * NBOX + lane + 32 * k], bacc[k]);

    // ---- last-block epilogue: loss + state reset ----
    __shared__ unsigned lastflag;
    __threadfence();
    if (t == 0) {
        unsigned vdone = atomicAdd(&g_done, 1u);
        lastflag = (vdone == (unsigned)(gridDim.x - 1));
    }
    __syncthreads();

    if (lastflag) {
        float sum = 0.0f;
#pragma unroll 4
        for (int i = t; i < BATCH * NBOX; i += NTHREADS) {
            float sv = __ldcg(&g_boxsum[i]);
            g_boxsum[i] = 0.0f;                 // reset for next replay
            float d = 1.0f - sv;                // invalid boxes stayed 0 -> contribute 1
            sum += (d > 0.0f) ? d : 0.0f;
        }
        __shared__ float red[WARPS];
#pragma unroll
        for (int o = 16; o; o >>= 1) sum += __shfl_down_sync(0xffffffffu, sum, o);
        if (lane == 0) red[w] = sum;
        __syncthreads();
        if (w == 0) {
            sum = (lane < WARPS) ? red[lane] : 0.0f;
#pragma unroll
            for (int o = 16; o; o >>= 1) sum += __shfl_down_sync(0xffffffffu, sum, o);
            if (lane == 0) {
                *out = sum;
                g_done = 0u;                    // reset counter for next replay
            }
        }
    }
}

extern "C" void kernel_launch(void* const* d_in, const int* in_sizes, int n_in,
                              void* d_out, int out_size) {
    const float* img = (const float*)d_in[0];   // (32,1,1024,1024) fp32
    const int*   bb  = (const int*)d_in[1];     // (32,96,4) int32
    float* out = (float*)d_out;

    fused_kernel<<<GRID, NTHREADS>>>(img, bb, out);
}

// round 16
// speedup vs baseline: 1.0296x; 1.0296x over previous
#include <cuda_runtime.h>

#define BATCH 32
#define IMH 1024
#define IMW 1024
#define NBOX 96
#define WARPS 8
#define NTHREADS 256
#define ROWS_PER_WARP 4
#define ROWS_PER_BLOCK (WARPS * ROWS_PER_WARP)   // 32
#define GRID (BATCH * IMH / ROWS_PER_BLOCK)      // 1024
#define EP_STRIDE 1032                           // >=1024, float4-aligned

// Per-(batch,box) rectangle sums. Zero-initialized at module load; the last
// block resets it after reading so every graph replay starts clean.
__device__ float    g_boxsum[BATCH * NBOX];
__device__ unsigned g_done;

__global__ __launch_bounds__(NTHREADS)
void fused_kernel(const float* __restrict__ img, const int* __restrict__ bb,
                  float* __restrict__ out) {
    __shared__ __align__(16) float ep_s[WARPS * EP_STRIDE];
    __shared__ int4 sbox[NBOX];

    const int t    = threadIdx.x;
    const int lane = t & 31;
    const int w    = t >> 5;
    const int blocksPerBatch = IMH / ROWS_PER_BLOCK;   // 32
    const int b       = blockIdx.x / blocksPerBatch;
    const int rowBase = (blockIdx.x % blocksPerBatch) * ROWS_PER_BLOCK + w * ROWS_PER_WARP;

    float* ep = ep_s + w * EP_STRIDE;

    const float4* imgrow = (const float4*)(img + (size_t)b * IMH * IMW);

    // First-row loads issued before the bbox sync (prologue overlap).
    float4 va[8];
#pragma unroll
    for (int j = 0; j < 8; j++)
        va[j] = imgrow[(size_t)rowBase * (IMW / 4) + lane + 32 * j];

    if (t < NBOX) sbox[t] = ((const int4*)bb)[b * NBOX + t];
    __syncthreads();

    // Each lane serves boxes lane, lane+32, lane+64. Packed state (3 regs/box):
    // px = x1 | x2<<16, py = y1 | y2<<16, bacc. Invalid boxes get y1=y2=0 ->
    // never served -> accumulate exactly 0, matching the reference mask.
    int   px[3], py[3];
    float bacc[3];
#pragma unroll
    for (int k = 0; k < 3; k++) {
        int4 box = sbox[lane + 32 * k];
        int x1 = min(max(box.x, 0), IMW);
        int y1 = min(max(box.y, 0), IMW);
        int x2 = min(max(box.z, 0), IMW);
        int y2 = min(max(box.w, 0), IMW);
        if (!((x2 > x1) && (y2 > y1))) { y1 = 0; y2 = 0; }
        px[k] = x1 | (x2 << 16);
        py[k] = y1 | (y2 << 16);
        bacc[k] = 0.0f;
    }

#pragma unroll
    for (int r = 0; r < ROWS_PER_WARP; ++r) {
        const int row = rowBase + r;

        // Register prefetch of next row (overlaps this row's scan).
        float4 vb[8];
        if (r + 1 < ROWS_PER_WARP) {
#pragma unroll
            for (int j = 0; j < 8; j++)
                vb[j] = imgrow[(size_t)(row + 1) * (IMW / 4) + lane + 32 * j];
        }

        // Per-(lane, segment) 4-element sums.
        float s[8], sc[8];
#pragma unroll
        for (int j = 0; j < 8; j++) {
            s[j]  = (va[j].x + va[j].y) + (va[j].z + va[j].w);
            sc[j] = s[j];
        }

        // Eight CONCURRENT Kogge-Stone scans (o-outer, j-inner: the 8
        // independent shfl chains pipeline in the SMSP).
#pragma unroll
        for (int o = 1; o < 32; o <<= 1) {
#pragma unroll
            for (int j = 0; j < 8; j++) {
                float u = __shfl_up_sync(0xffffffffu, sc[j], o);
                if (lane >= o) sc[j] += u;
            }
        }

        // Segment totals via 8 parallel broadcasts + short scalar prefix.
        float T[8];
#pragma unroll
        for (int j = 0; j < 8; j++)
            T[j] = __shfl_sync(0xffffffffu, sc[j], 31);
        float basej[8];
        basej[0] = 0.0f;
#pragma unroll
        for (int j = 1; j < 8; j++)
            basej[j] = basej[j - 1] + T[j - 1];
        const float rowtot = basej[7] + T[7];   // warp-uniform: prefix(1024)

        // Write exclusive prefixes: 8 conflict-free STS.128 per row.
#pragma unroll
        for (int j = 0; j < 8; j++) {
            float excl = (sc[j] - s[j]) + basej[j];
            float4 p;
            p.x = excl;
            p.y = p.x + va[j].x;
            p.z = p.y + va[j].y;
            p.w = p.z + va[j].z;
            *(float4*)(ep + 128 * j + 4 * lane) = p;
        }
        __syncwarp();

        // Serve this row for all 96 boxes (3 per lane). Single unsigned
        // compare for the y-range; x2==1024 uses the register row total.
#pragma unroll
        for (int k = 0; k < 3; k++) {
            const int y1 = py[k] & 0xffff;
            if ((unsigned)(row - y1) < (unsigned)((py[k] >> 16) - y1)) {
                const int x1 = px[k] & 0xffff, x2 = px[k] >> 16;
                float right = (x2 == IMW) ? rowtot : ep[x2];
                bacc[k] += right - ep[x1];
            }
        }
        __syncwarp();   // ep reused next row

        if (r + 1 < ROWS_PER_WARP) {
#pragma unroll
            for (int j = 0; j < 8; j++)
                va[j] = vb[j];
        }
    }

#pragma unroll
    for (int k = 0; k < 3; k++)
        if (bacc[k] != 0.0f)
            atomicAdd(&g_boxsum[b * NBOX + lane + 32 * k], bacc[k]);

    // ---- last-block epilogue: loss + state reset ----
    __shared__ unsigned lastflag;
    __threadfence();
    if (t == 0) {
        unsigned vdone = atomicAdd(&g_done, 1u);
        lastflag = (vdone == (unsigned)(gridDim.x - 1));
    }
    __syncthreads();

    if (lastflag) {
        float sum = 0.0f;
#pragma unroll 4
        for (int i = t; i < BATCH * NBOX; i += NTHREADS) {
            float sv = __ldcg(&g_boxsum[i]);
            g_boxsum[i] = 0.0f;                 // reset for next replay
            float d = 1.0f - sv;                // invalid boxes stayed 0 -> contribute 1
            sum += (d > 0.0f) ? d : 0.0f;
        }
        __shared__ float red[WARPS];
#pragma unroll
        for (int o = 16; o; o >>= 1) sum += __shfl_down_sync(0xffffffffu, sum, o);
        if (lane == 0) red[w] = sum;
        __syncthreads();
        if (w == 0) {
            sum = (lane < WARPS) ? red[lane] : 0.0f;
#pragma unroll
            for (int o = 16; o; o >>= 1) sum += __shfl_down_sync(0xffffffffu, sum, o);
            if (lane == 0) {
                *out = sum;
                g_done = 0u;                    // reset counter for next replay
            }
        }
    }
}

extern "C" void kernel_launch(void* const* d_in, const int* in_sizes, int n_in,
                              void* d_out, int out_size) {
    const float* img = (const float*)d_in[0];   // (32,1,1024,1024) fp32
    const int*   bb  = (const int*)d_in[1];     // (32,96,4) int32
    float* out = (float*)d_out;

    fused_kernel<<<GRID, NTHREADS>>>(img, bb, out);
}

// round 17
// speedup vs baseline: 1.1045x; 1.0727x over previous
#include <cuda_runtime.h>

#define BATCH 32
#define IMH 1024
#define IMW 1024
#define NBOX 96
#define WARPS 8
#define NTHREADS 256
#define ROWS_PER_WARP 4
#define ROWS_PER_BLOCK (WARPS * ROWS_PER_WARP)   // 32
#define GRID (BATCH * IMH / ROWS_PER_BLOCK)      // 1024
#define EP_STRIDE 1032                           // >=1025, float4-aligned

// Per-(batch,box) rectangle sums. Zero-initialized at module load; the last
// block resets it after reading so every graph replay starts clean.
__device__ float    g_boxsum[BATCH * NBOX];
__device__ unsigned g_done;

__global__ __launch_bounds__(NTHREADS)
void fused_kernel(const float* __restrict__ img, const int* __restrict__ bb,
                  float* __restrict__ out) {
    __shared__ __align__(16) float ep_s[WARPS * EP_STRIDE];
    __shared__ int4 sbox[NBOX];

    const int t    = threadIdx.x;
    const int lane = t & 31;
    const int w    = t >> 5;
    const int blocksPerBatch = IMH / ROWS_PER_BLOCK;   // 32
    const int b       = blockIdx.x / blocksPerBatch;
    const int rowBase = (blockIdx.x % blocksPerBatch) * ROWS_PER_BLOCK + w * ROWS_PER_WARP;

    float* ep = ep_s + w * EP_STRIDE;

    const float4* imgrow = (const float4*)(img + (size_t)b * IMH * IMW);

    // First-row loads issued before the bbox sync (prologue overlap).
    float4 va[8];
#pragma unroll
    for (int j = 0; j < 8; j++)
        va[j] = imgrow[(size_t)rowBase * (IMW / 4) + lane + 32 * j];

    if (t < NBOX) sbox[t] = ((const int4*)bb)[b * NBOX + t];
    __syncthreads();

    // Each lane serves boxes lane, lane+32, lane+64.
    int   bx1[3], bx2[3], by1[3], by2[3];
    bool  bval[3];
    float bacc[3];
#pragma unroll
    for (int k = 0; k < 3; k++) {
        int4 box = sbox[lane + 32 * k];
        bx1[k] = min(max(box.x, 0), IMW);
        by1[k] = min(max(box.y, 0), IMW);
        bx2[k] = min(max(box.z, 0), IMW);
        by2[k] = min(max(box.w, 0), IMW);
        bval[k] = (bx2[k] > bx1[k]) && (by2[k] > by1[k]);
        bacc[k] = 0.0f;
    }

#pragma unroll
    for (int r = 0; r < ROWS_PER_WARP; ++r) {
        const int row = rowBase + r;

        // Register prefetch of next row (overlaps this row's scan).
        float4 vb[8];
        if (r + 1 < ROWS_PER_WARP) {
#pragma unroll
            for (int j = 0; j < 8; j++)
                vb[j] = imgrow[(size_t)(row + 1) * (IMW / 4) + lane + 32 * j];
        }

        // Per-(lane, segment) 4-element sums.
        float s[8], sc[8];
#pragma unroll
        for (int j = 0; j < 8; j++) {
            s[j]  = (va[j].x + va[j].y) + (va[j].z + va[j].w);
            sc[j] = s[j];
        }

        // EIGHT CONCURRENT Kogge-Stone scans: o-outer, j-inner so the 8
        // independent shfl chains pipeline in the SMSP (latency ~5*26 total,
        // not 8 serialized scans).
#pragma unroll
        for (int o = 1; o < 32; o <<= 1) {
#pragma unroll
            for (int j = 0; j < 8; j++) {
                float u = __shfl_up_sync(0xffffffffu, sc[j], o);
                if (lane >= o) sc[j] += u;
            }
        }

        // Segment totals via 8 parallel broadcasts, then a short scalar
        // exclusive prefix over the 8 totals (7 FADDs).
        float T[8];
#pragma unroll
        for (int j = 0; j < 8; j++)
            T[j] = __shfl_sync(0xffffffffu, sc[j], 31);
        float basej[8];
        basej[0] = 0.0f;
#pragma unroll
        for (int j = 1; j < 8; j++)
            basej[j] = basej[j - 1] + T[j - 1];
        const float rowtot = basej[7] + T[7];

        // Write exclusive prefixes: 8 conflict-free STS.128 per row.
#pragma unroll
        for (int j = 0; j < 8; j++) {
            float excl = (sc[j] - s[j]) + basej[j];
            float4 p;
            p.x = excl;
            p.y = p.x + va[j].x;
            p.z = p.y + va[j].y;
            p.w = p.z + va[j].z;
            *(float4*)(ep + 128 * j + 4 * lane) = p;
        }
        if (lane == 31) ep[IMW] = rowtot;
        __syncwarp();

        // Serve this row for all 96 boxes (3 per lane).
#pragma unroll
        for (int k = 0; k < 3; k++) {
            if (bval[k] && by1[k] <= row && row < by2[k])
                bacc[k] += ep[bx2[k]] - ep[bx1[k]];
        }
        __syncwarp();   // ep reused next row

        if (r + 1 < ROWS_PER_WARP) {
#pragma unroll
            for (int j = 0; j < 8; j++)
                va[j] = vb[j];
        }
    }

#pragma unroll
    for (int k = 0; k < 3; k++)
        if (bval[k] && bacc[k] != 0.0f)
            atomicAdd(&g_boxsum[b * NBOX + lane + 32 * k], bacc[k]);

    // ---- last-block epilogue: loss + state reset ----
    __shared__ unsigned lastflag;
    __threadfence();
    if (t == 0) {
        unsigned vdone = atomicAdd(&g_done, 1u);
        lastflag = (vdone == (unsigned)(gridDim.x - 1));
    }
    __syncthreads();

    if (lastflag) {
        float sum = 0.0f;
#pragma unroll 4
        for (int i = t; i < BATCH * NBOX; i += NTHREADS) {
            float sv = __ldcg(&g_boxsum[i]);
            g_boxsum[i] = 0.0f;                 // reset for next replay
            float d = 1.0f - sv;                // invalid boxes stayed 0 -> contribute 1
            sum += (d > 0.0f) ? d : 0.0f;
        }
        __shared__ float red[WARPS];
#pragma unroll
        for (int o = 16; o; o >>= 1) sum += __shfl_down_sync(0xffffffffu, sum, o);
        if (lane == 0) red[w] = sum;
        __syncthreads();
        if (w == 0) {
            sum = (lane < WARPS) ? red[lane] : 0.0f;
#pragma unroll
            for (int o = 16; o; o >>= 1) sum += __shfl_down_sync(0xffffffffu, sum, o);
            if (lane == 0) {
                *out = sum;
                g_done = 0u;                    // reset counter for next replay
            }
        }
    }
}

extern "C" void kernel_launch(void* const* d_in, const int* in_sizes, int n_in,
                              void* d_out, int out_size) {
    const float* img = (const float*)d_in[0];   // (32,1,1024,1024) fp32
    const int*   bb  = (const int*)d_in[1];     // (32,96,4) int32
    float* out = (float*)d_out;

    fused_kernel<<<GRID, NTHREADS>>>(img, bb, out);
}